// round 9
// baseline (speedup 1.0000x reference)
#include <cuda_runtime.h>
#include <cmath>

#define NN 50000
#define EE 800000
typedef unsigned long long u64;

// ---------------- f32x2 helpers ----------------------------------------------------
__device__ __forceinline__ u64 pk2(float lo, float hi) {
    u64 r; asm("mov.b64 %0, {%1,%2};" : "=l"(r) : "f"(lo), "f"(hi)); return r;
}
__device__ __forceinline__ void up2(float& lo, float& hi, u64 v) {
    asm("mov.b64 {%0,%1}, %2;" : "=f"(lo), "=f"(hi) : "l"(v));
}
__device__ __forceinline__ u64 fma2(u64 a, u64 b, u64 c) {
    u64 d; asm("fma.rn.f32x2 %0, %1, %2, %3;" : "=l"(d) : "l"(a), "l"(b), "l"(c)); return d;
}
__device__ __forceinline__ u64 add2(u64 a, u64 b) {
    u64 d; asm("add.rn.f32x2 %0, %1, %2;" : "=l"(d) : "l"(a), "l"(b)); return d;
}

// ---------------- global scratch ---------------------------------------------------
__device__ __align__(16) u64 g_etab2[5 * 34];           // channel pairs (c, c+32), row stride 34
__device__ __align__(16) u64 g_adst2[NN * 32];          // interleaved (c, c+32)
__device__ __align__(16) u64 g_asrc2[NN * 32];
__device__ int   g_deg[NN];
__device__ __align__(16) int g_rowoff[NN + 4];
__device__ __align__(16) int g_cursor[NN + 4];
__device__ int   g_epack[EE];                           // per CSR slot: src | bond<<16
__device__ __align__(16) float g_agg[NN * 320];

#define NB1 ((NN + 127) / 128)

// ---------------- K1': node pre-transforms + bond tables + deg zero ----------------
__global__ void k1_nodepre(const float* __restrict__ atom_x, const float* __restrict__ pre_w1,
                           const float* __restrict__ bond_emb, const float* __restrict__ edge_w,
                           const float* __restrict__ edge_b, const float* __restrict__ pre_b1) {
    if (blockIdx.x == NB1) {
        __shared__ float eraw[5 * 16];
        int tid = threadIdx.x;
        if (tid < 80) {
            int b = tid / 16, f = tid % 16;
            float acc = edge_b[f];
            for (int h = 0; h < 64; h++) acc += bond_emb[b * 64 + h] * edge_w[h * 16 + f];
            eraw[b * 16 + f] = acc;
        }
        __syncthreads();
        for (int i = tid; i < 160; i += blockDim.x) {
            int b = i / 32, c = i % 32;                 // channel pair (c, c+32)
            int t = c / 16, g = c % 16;
            float v1 = pre_b1[t * 16 + g];
            float v2 = pre_b1[(t + 2) * 16 + g];
            for (int f = 0; f < 16; f++) {
                v1 += eraw[b * 16 + f] * pre_w1[t * 768 + (32 + f) * 16 + g];
                v2 += eraw[b * 16 + f] * pre_w1[(t + 2) * 768 + (32 + f) * 16 + g];
            }
            g_etab2[b * 34 + c] = pk2(v1, v2);
        }
        return;
    }

    __shared__ float w1s[3072];
    for (int i = threadIdx.x; i < 3072; i += blockDim.x) w1s[i] = pre_w1[i];
    __syncthreads();
    int n = blockIdx.x * blockDim.x + threadIdx.x;
    if (n >= NN) return;
    g_deg[n] = 0;

#pragma unroll
    for (int t1 = 0; t1 < 2; t1++) {
        int ta = t1, tb = t1 + 2;
        float xa[16], xb[16];
        const float4* xpa = (const float4*)(atom_x + (size_t)n * 64 + ta * 16);
        const float4* xpb = (const float4*)(atom_x + (size_t)n * 64 + tb * 16);
#pragma unroll
        for (int q = 0; q < 4; q++) {
            float4 v = xpa[q];
            xa[4*q] = v.x; xa[4*q+1] = v.y; xa[4*q+2] = v.z; xa[4*q+3] = v.w;
            float4 w = xpb[q];
            xb[4*q] = w.x; xb[4*q+1] = w.y; xb[4*q+2] = w.z; xb[4*q+3] = w.w;
        }
        float ada[16], asa[16], adb[16], asb[16];
#pragma unroll
        for (int g = 0; g < 16; g++) { ada[g]=0.f; asa[g]=0.f; adb[g]=0.f; asb[g]=0.f; }
#pragma unroll
        for (int f = 0; f < 16; f++) {
            float va = xa[f], vb = xb[f];
#pragma unroll
            for (int g = 0; g < 16; g++) {
                ada[g] += va * w1s[ta * 768 + f * 16 + g];
                asa[g] += va * w1s[ta * 768 + (16 + f) * 16 + g];
                adb[g] += vb * w1s[tb * 768 + f * 16 + g];
                asb[g] += vb * w1s[tb * 768 + (16 + f) * 16 + g];
            }
        }
#pragma unroll
        for (int g = 0; g < 16; g++) {
            g_adst2[(size_t)n * 32 + t1 * 16 + g] = pk2(ada[g], adb[g]);
            g_asrc2[(size_t)n * 32 + t1 * 16 + g] = pk2(asa[g], asb[g]);
        }
    }
}

// ---------------- K2: degree histogram ---------------------------------------------
__global__ void k2_count(const int* __restrict__ dst) {
    int e = blockIdx.x * blockDim.x + threadIdx.x;
    if (e < EE) atomicAdd(&g_deg[dst[e]], 1);
}

// ---------------- K3: exclusive scan (single block, int4) --------------------------
__global__ void k3_scan() {
    __shared__ int wsum[32];
    __shared__ int s_tot;
    int tid = threadIdx.x, lane = tid & 31, wid = tid >> 5;
    int running = 0;
    for (int base = 0; base < NN; base += 4096) {
        int i0 = base + tid * 4;
        int4 v = make_int4(0, 0, 0, 0);
        if (i0 < NN) v = *(const int4*)&g_deg[i0];
        int c0 = v.x, c1 = c0 + v.y, c2 = c1 + v.z, c3 = c2 + v.w;
        int tsum = c3;
        int incl = tsum;
#pragma unroll
        for (int d = 1; d < 32; d <<= 1) {
            int t2 = __shfl_up_sync(0xFFFFFFFFu, incl, d);
            if (lane >= d) incl += t2;
        }
        if (lane == 31) wsum[wid] = incl;
        __syncthreads();
        if (wid == 0) {
            int wv = wsum[lane];
            int wi = wv;
#pragma unroll
            for (int d = 1; d < 32; d <<= 1) {
                int t2 = __shfl_up_sync(0xFFFFFFFFu, wi, d);
                if (lane >= d) wi += t2;
            }
            wsum[lane] = wi - wv;
            if (lane == 31) s_tot = wi;
        }
        __syncthreads();
        int off = running + wsum[wid] + incl - tsum;
        if (i0 < NN) {
            int4 o = make_int4(off, off + c0, off + c1, off + c2);
            *(int4*)&g_rowoff[i0] = o;
            *(int4*)&g_cursor[i0] = o;
        }
        running += s_tot;
        __syncthreads();
    }
    if (tid == 0) g_rowoff[NN] = running;
}

// ---------------- K4: bucket permutation + pack ------------------------------------
__global__ void k4_permute(const int* __restrict__ src, const int* __restrict__ dst,
                           const int* __restrict__ bond) {
    int e = blockIdx.x * blockDim.x + threadIdx.x;
    if (e >= EE) return;
    int slot = atomicAdd(&g_cursor[dst[e]], 1);
    g_epack[slot] = src[e] | (bond[e] << 16);
}

// ---------------- K5: fused edge messages + aggregation (f32x2, smem h-broadcast) --
__global__ void __launch_bounds__(256) k5_edgeagg(const float* __restrict__ pre_w2,
                                                  const float* __restrict__ pre_b2) {
    __shared__ float w2s[1024];
    __shared__ float b2s[64];
    __shared__ u64 etab2s[5 * 34];
    __shared__ u64 hbuf[8][2][32];
    for (int i = threadIdx.x; i < 1024; i += blockDim.x) w2s[i] = pre_w2[i];
    for (int i = threadIdx.x; i < 64; i += blockDim.x) b2s[i] = pre_b2[i];
    for (int i = threadIdx.x; i < 170; i += blockDim.x) etab2s[i] = g_etab2[i];
    __syncthreads();

    int wid = threadIdx.x >> 5, lane = threadIdx.x & 31;
    int n = blockIdx.x * 8 + wid;
    if (n >= NN) return;

    int t1 = (lane >> 4) & 1, f1 = lane & 15;
    int sb = lane & 16;

    u64 wp[16];
#pragma unroll
    for (int f = 0; f < 16; f++)
        wp[f] = pk2(w2s[t1 * 256 + f * 16 + f1], w2s[(t1 + 2) * 256 + f * 16 + f1]);
    u64 b2p   = pk2(b2s[lane], b2s[lane + 32]);
    u64 adstp = g_adst2[(size_t)n * 32 + lane];

    int r0 = g_rowoff[n], r1 = g_rowoff[n + 1];
    u64 sx = 0, qx = 0;
    float mn1 = INFINITY, mn2 = INFINITY, mx1 = -INFINITY, mx2 = -INFINITY;

    for (int i = r0; i < r1; i += 32) {
        int pk = 0;
        if (i + lane < r1) pk = g_epack[i + lane];
        int cnt = min(32, r1 - i);
        int p0 = __shfl_sync(0xFFFFFFFFu, pk, 0);
        u64 a0 = __ldg(&g_asrc2[(size_t)(p0 & 0xFFFF) * 32 + lane]);
        int p1 = p0; u64 a1 = a0;
        if (cnt > 1) {
            p1 = __shfl_sync(0xFFFFFFFFu, pk, 1);
            a1 = __ldg(&g_asrc2[(size_t)(p1 & 0xFFFF) * 32 + lane]);
        }
        for (int j = 0; j < cnt; j++) {
            u64 acur = a0; int pcur = p0;
            a0 = a1; p0 = p1;
            if (j + 2 < cnt) {
                p1 = __shfl_sync(0xFFFFFFFFu, pk, j + 2);
                a1 = __ldg(&g_asrc2[(size_t)(p1 & 0xFFFF) * 32 + lane]);
            }
            u64 hsum = add2(adstp, add2(acur, etab2s[(pcur >> 16) * 34 + lane]));
            float hl, hh; up2(hl, hh, hsum);
            hl = fmaxf(hl, 0.f); hh = fmaxf(hh, 0.f);
            hbuf[wid][j & 1][lane] = pk2(hl, hh);
            __syncwarp();
            const u64* hb = &hbuf[wid][j & 1][sb];
            // two independent accumulator chains (halve dep latency)
            u64 mA = b2p, mB = 0;
#pragma unroll
            for (int f = 0; f < 8; f++) {
                mA = fma2(hb[2 * f],     wp[2 * f],     mA);
                mB = fma2(hb[2 * f + 1], wp[2 * f + 1], mB);
            }
            u64 m2 = add2(mA, mB);
            sx = add2(sx, m2);
            qx = fma2(m2, m2, qx);
            float mv1, mv2; up2(mv1, mv2, m2);
            mn1 = fminf(mn1, mv1); mx1 = fmaxf(mx1, mv1);
            mn2 = fminf(mn2, mv2); mx2 = fmaxf(mx2, mv2);
        }
    }

    float s1, s2, q1, q2;
    up2(s1, s2, sx); up2(q1, q2, qx);
    int deg = r1 - r0;
    float cc = fmaxf((float)deg, 1.f);
    float inv = 1.f / cc;
    float mean1 = s1 * inv, mean2 = s2 * inv;
    float std1 = sqrtf(fmaxf(q1 * inv - mean1 * mean1, 0.f) + 1e-5f);
    float std2 = sqrtf(fmaxf(q2 * inv - mean2 * mean2, 0.f) + 1e-5f);
    if (deg == 0) { mn1 = 0.f; mn2 = 0.f; mx1 = 0.f; mx2 = 0.f; }

    float* ap = g_agg + (size_t)n * 320 + t1 * 80 + f1;
    ap[0]  = s1;  ap[16] = mean1; ap[32] = mn1; ap[48] = mx1; ap[64] = std1;
    float* cp = g_agg + (size_t)n * 320 + (t1 + 2) * 80 + f1;
    cp[0]  = s2;  cp[16] = mean2; cp[32] = mn2; cp[48] = mx2; cp[64] = std2;
}

// ---------------- K6: post-MLP + lin + LN + residual (f32x2, conflict-free strides) -
// floats: w1t 64*250=16000 @0 | w1h 1024 @16000 | w2s 1024 @17024 | lwsT 64*66=4224 @18048
//         bias 320 @22272 | scratch 16*2056 @22592
#define K6_W1T  0
#define K6_W1ST 250
#define K6_W1H  16000
#define K6_W2   17024
#define K6_LWT  18048
#define K6_BIAS 22272
#define K6_SCR  22592
#define K6_SMEM_FLOATS (K6_SCR + 16 * 2056)

__global__ void __launch_bounds__(512, 1)
k6_node(const float* __restrict__ atom_x,
        const float* __restrict__ post_w1, const float* __restrict__ post_b1,
        const float* __restrict__ post_w2, const float* __restrict__ post_b2,
        const float* __restrict__ lin_w, const float* __restrict__ lin_b,
        const float* __restrict__ ln_g, const float* __restrict__ ln_b,
        float* __restrict__ out, float avg_log) {
    extern __shared__ float sm[];
    float* w1t  = sm + K6_W1T;
    float* w1h  = sm + K6_W1H;
    float* w2s  = sm + K6_W2;
    float* lwsT = sm + K6_LWT;
    float* bias = sm + K6_BIAS;
    float* scratch = sm + K6_SCR;

    int tid = threadIdx.x;
    // phase 1: coalesced raw loads into scratch
    for (int i = tid; i < 16384; i += 512) scratch[i] = post_w1[i];
    for (int i = tid; i < 4096; i += 512) scratch[16384 + i] = lin_w[i];
    for (int i = tid; i < 1024; i += 512) w2s[i] = post_w2[i];
    if (tid < 64) {
        bias[tid]       = post_b1[tid];
        bias[64 + tid]  = post_b2[tid];
        bias[128 + tid] = lin_b[tid];
        bias[192 + tid] = ln_g[tid];
        bias[256 + tid] = ln_b[tid];
    }
    __syncthreads();
    // phase 2: transposed layouts (row stride 250 -> 2-way = crossbar floor)
    for (int i = tid; i < 15360; i += 512) {
        int k = i % 80, s = (i / 80) % 3, chan = i / 240;
        int t = chan >> 4, g = chan & 15;
        w1t[chan * K6_W1ST + s * 82 + k] = scratch[t * 4096 + (16 + s * 80 + k) * 16 + g];
    }
    for (int i = tid; i < 1024; i += 512) {
        int t = i >> 8, r = (i >> 4) & 15, g = i & 15;
        w1h[i] = scratch[t * 4096 + r * 16 + g];
    }
    for (int i = tid; i < 4096; i += 512) {
        int k = i >> 6, o = i & 63;
        lwsT[o * 66 + k] = scratch[16384 + k * 64 + o];
    }
    __syncthreads();

    int wid = tid >> 5, lane = tid & 31;
    int nb = blockIdx.x * 64 + wid * 4;

    float* ws = scratch + wid * 2056;
    // layout: xts[4*64] | basev[4*320]@256 | hids[4*64]@1536 | hid2[4*64]@1792 | sc[8]@2048

#pragma unroll
    for (int m = 0; m < 4; m++) {
        int n = nb + m;
        if (n < NN) {
            ws[m * 64 + lane]      = atom_x[(size_t)n * 64 + lane];
            ws[m * 64 + lane + 32] = atom_x[(size_t)n * 64 + lane + 32];
            const float* agp = g_agg + (size_t)n * 320;
#pragma unroll
            for (int i = 0; i < 10; i++) ws[256 + m * 320 + lane + 32 * i] = agp[lane + 32 * i];
            if (lane == 0) {
                float cc = fmaxf((float)g_deg[n], 1.f);
                float ldv = logf(cc + 1.f);
                ws[2048 + m * 2]     = ldv / avg_log;
                ws[2048 + m * 2 + 1] = avg_log / ldv;
            }
        }
    }
    __syncwarp();

    int t1 = lane >> 4, f1 = lane & 15;
    int t2 = t1 + 2;
    int chan1 = t1 * 16 + f1;       // == lane
    int chan2 = chan1 + 32;

    // ---- layer 1 head (x part, scalar) ----
    float hA[4], hB[4];
#pragma unroll
    for (int m = 0; m < 4; m++) { hA[m] = 0.f; hB[m] = 0.f; }
#pragma unroll 4
    for (int f = 0; f < 16; f++) {
        float wa = w1h[t1 * 256 + f * 16 + f1];
        float wb = w1h[t2 * 256 + f * 16 + f1];
#pragma unroll
        for (int m = 0; m < 4; m++) {
            hA[m] += ws[m * 64 + t1 * 16 + f] * wa;
            hB[m] += ws[m * 64 + t2 * 16 + f] * wb;
        }
    }

    // ---- layer 1 agg part (f32x2 over k-pairs) ----
    u64 aA[4], aB[4], aC[4], bA[4], bB[4], bC[4];
#pragma unroll
    for (int m = 0; m < 4; m++) { aA[m]=0; aB[m]=0; aC[m]=0; bA[m]=0; bB[m]=0; bC[m]=0; }
    const float* W1c1 = w1t + chan1 * K6_W1ST;
    const float* W1c2 = w1t + chan2 * K6_W1ST;
#pragma unroll 2
    for (int kk = 0; kk < 80; kk += 2) {
        u64 wa1 = *(const u64*)(W1c1 + kk);
        u64 wb1 = *(const u64*)(W1c1 + 82 + kk);
        u64 wc1 = *(const u64*)(W1c1 + 164 + kk);
        u64 wa2 = *(const u64*)(W1c2 + kk);
        u64 wb2 = *(const u64*)(W1c2 + 82 + kk);
        u64 wc2 = *(const u64*)(W1c2 + 164 + kk);
#pragma unroll
        for (int m = 0; m < 4; m++) {
            u64 v1 = *(const u64*)(ws + 256 + m * 320 + t1 * 80 + kk);
            u64 v2 = *(const u64*)(ws + 256 + m * 320 + t2 * 80 + kk);
            aA[m] = fma2(v1, wa1, aA[m]); aB[m] = fma2(v1, wb1, aB[m]); aC[m] = fma2(v1, wc1, aC[m]);
            bA[m] = fma2(v2, wa2, bA[m]); bB[m] = fma2(v2, wb2, bB[m]); bC[m] = fma2(v2, wc2, bC[m]);
        }
    }
#pragma unroll
    for (int m = 0; m < 4; m++) {
        float sc1 = ws[2048 + m * 2], sc2 = ws[2048 + m * 2 + 1];
        float lo, hi;
        up2(lo, hi, aA[m]); float dA = hA[m] + lo + hi;
        up2(lo, hi, aB[m]); float dB = lo + hi;
        up2(lo, hi, aC[m]); float dC = lo + hi;
        float acc1 = bias[lane] + dA + sc1 * dB + sc2 * dC;
        up2(lo, hi, bA[m]); float eA = hB[m] + lo + hi;
        up2(lo, hi, bB[m]); float eB = lo + hi;
        up2(lo, hi, bC[m]); float eC = lo + hi;
        float acc2 = bias[lane + 32] + eA + sc1 * eB + sc2 * eC;
        ws[1536 + m * 64 + lane]      = fmaxf(acc1, 0.f);
        ws[1536 + m * 64 + lane + 32] = fmaxf(acc2, 0.f);
    }
    __syncwarp();

    // ---- layer 2 (scalar, small) ----
    {
        float a1[4], a2[4];
#pragma unroll
        for (int m = 0; m < 4; m++) { a1[m] = bias[64 + lane]; a2[m] = bias[64 + lane + 32]; }
#pragma unroll 4
        for (int f = 0; f < 16; f++) {
            float w_1 = w2s[t1 * 256 + f * 16 + f1];
            float w_2 = w2s[t2 * 256 + f * 16 + f1];
#pragma unroll
            for (int m = 0; m < 4; m++) {
                a1[m] += ws[1536 + m * 64 + t1 * 16 + f] * w_1;
                a2[m] += ws[1536 + m * 64 + t2 * 16 + f] * w_2;
            }
        }
        __syncwarp();
#pragma unroll
        for (int m = 0; m < 4; m++) {
            ws[1792 + m * 64 + lane]      = a1[m];
            ws[1792 + m * 64 + lane + 32] = a2[m];
        }
        __syncwarp();
    }

    // ---- final linear (f32x2 over k-pairs) ----
    u64 p1[4], p2[4];
#pragma unroll
    for (int m = 0; m < 4; m++) { p1[m] = 0; p2[m] = 0; }
    const float* LT1 = lwsT + lane * 66;
    const float* LT2 = lwsT + (lane + 32) * 66;
#pragma unroll 4
    for (int kk = 0; kk < 64; kk += 2) {
        u64 wq1 = *(const u64*)(LT1 + kk);
        u64 wq2 = *(const u64*)(LT2 + kk);
#pragma unroll
        for (int m = 0; m < 4; m++) {
            u64 hv = *(const u64*)(ws + 1792 + m * 64 + kk);
            p1[m] = fma2(hv, wq1, p1[m]);
            p2[m] = fma2(hv, wq2, p2[m]);
        }
    }

    // ---- LayerNorm + ReLU + residual ----
#pragma unroll
    for (int m = 0; m < 4; m++) {
        int n = nb + m;
        float lo, hi;
        up2(lo, hi, p1[m]); float v1 = bias[128 + lane] + lo + hi;
        up2(lo, hi, p2[m]); float v2 = bias[128 + lane + 32] + lo + hi;
        float ssum = v1 + v2;
#pragma unroll
        for (int d = 16; d; d >>= 1) ssum += __shfl_xor_sync(0xFFFFFFFFu, ssum, d);
        float mu = ssum * (1.f / 64.f);
        float d1 = v1 - mu, d2 = v2 - mu;
        float vs = d1 * d1 + d2 * d2;
#pragma unroll
        for (int d = 16; d; d >>= 1) vs += __shfl_xor_sync(0xFFFFFFFFu, vs, d);
        float rstd = rsqrtf(vs * (1.f / 64.f) + 1e-5f);
        float o1 = d1 * rstd * bias[192 + lane] + bias[256 + lane];
        float o2 = d2 * rstd * bias[192 + lane + 32] + bias[256 + lane + 32];
        if (n < NN) {
            out[(size_t)n * 64 + lane]      = ws[m * 64 + lane]      + fmaxf(o1, 0.f);
            out[(size_t)n * 64 + lane + 32] = ws[m * 64 + lane + 32] + fmaxf(o2, 0.f);
        }
    }
}

// ---------------- launch -----------------------------------------------------------
extern "C" void kernel_launch(void* const* d_in, const int* in_sizes, int n_in,
                              void* d_out, int out_size) {
    const float* atom_x  = (const float*)d_in[0];
    const float* bond_emb= (const float*)d_in[1];
    const float* edge_w  = (const float*)d_in[2];
    const float* edge_b  = (const float*)d_in[3];
    const float* pre_w1  = (const float*)d_in[4];
    const float* pre_b1  = (const float*)d_in[5];
    const float* pre_w2  = (const float*)d_in[6];
    const float* pre_b2  = (const float*)d_in[7];
    const float* post_w1 = (const float*)d_in[8];
    const float* post_b1 = (const float*)d_in[9];
    const float* post_w2 = (const float*)d_in[10];
    const float* post_b2 = (const float*)d_in[11];
    const float* lin_w   = (const float*)d_in[12];
    const float* lin_b   = (const float*)d_in[13];
    const float* ln_g    = (const float*)d_in[14];
    const float* ln_b    = (const float*)d_in[15];
    const int*   bond_x  = (const int*)d_in[16];
    const int*   aei     = (const int*)d_in[17];
    const int*   srcp = aei;
    const int*   dstp = aei + EE;
    float* out = (float*)d_out;

    double md[9] = {0, 5, 15, 30, 25, 15, 7, 2, 1};
    double sacc = 0.0, wacc = 0.0;
    for (int i = 0; i < 9; i++) { sacc += std::log((double)i + 1.0) * md[i]; wacc += md[i]; }
    float avg_log = (float)(sacc / wacc);

    const int k6_smem = K6_SMEM_FLOATS * 4;
    cudaFuncSetAttribute(k6_node, cudaFuncAttributeMaxDynamicSharedMemorySize, k6_smem);

    k1_nodepre<<<NB1 + 1, 128>>>(atom_x, pre_w1, bond_emb, edge_w, edge_b, pre_b1);
    k2_count<<<(EE + 255) / 256, 256>>>(dstp);
    k3_scan<<<1, 1024>>>();
    k4_permute<<<(EE + 255) / 256, 256>>>(srcp, dstp, bond_x);
    k5_edgeagg<<<(NN + 7) / 8, 256>>>(pre_w2, pre_b2);
    k6_node<<<(NN + 63) / 64, 512, k6_smem>>>(atom_x, post_w1, post_b1, post_w2, post_b2,
                                              lin_w, lin_b, ln_g, ln_b, out, avg_log);
}

// round 13
// speedup vs baseline: 1.2478x; 1.2478x over previous
#include <cuda_runtime.h>
#include <cmath>

#define NN 50000
#define EE 800000
typedef unsigned long long u64;

// ---------------- f32x2 helpers (used in k1/k5 h-compute only) ---------------------
__device__ __forceinline__ u64 pk2(float lo, float hi) {
    u64 r; asm("mov.b64 %0, {%1,%2};" : "=l"(r) : "f"(lo), "f"(hi)); return r;
}
__device__ __forceinline__ void up2(float& lo, float& hi, u64 v) {
    asm("mov.b64 {%0,%1}, %2;" : "=f"(lo), "=f"(hi) : "l"(v));
}
__device__ __forceinline__ u64 add2(u64 a, u64 b) {
    u64 d; asm("add.rn.f32x2 %0, %1, %2;" : "=l"(d) : "l"(a), "l"(b)); return d;
}

// ---------------- global scratch ---------------------------------------------------
__device__ __align__(16) u64 g_etab2[5 * 34];           // channel pairs (c, c+32), row stride 34
__device__ __align__(16) u64 g_adst2[NN * 32];          // interleaved (c, c+32)
__device__ __align__(16) u64 g_asrc2[NN * 32];
__device__ int   g_deg[NN];
__device__ __align__(16) int g_rowoff[NN + 4];
__device__ __align__(16) int g_cursor[NN + 4];
__device__ int   g_epack[EE];                           // per CSR slot: src | bond<<16
__device__ __align__(16) float g_agg[NN * 320];

#define NB1 ((NN + 127) / 128)

// ---------------- K1': node pre-transforms + bond tables + deg zero ----------------
__global__ void k1_nodepre(const float* __restrict__ atom_x, const float* __restrict__ pre_w1,
                           const float* __restrict__ bond_emb, const float* __restrict__ edge_w,
                           const float* __restrict__ edge_b, const float* __restrict__ pre_b1) {
    if (blockIdx.x == NB1) {
        __shared__ float eraw[5 * 16];
        int tid = threadIdx.x;
        if (tid < 80) {
            int b = tid / 16, f = tid % 16;
            float acc = edge_b[f];
            for (int h = 0; h < 64; h++) acc += bond_emb[b * 64 + h] * edge_w[h * 16 + f];
            eraw[b * 16 + f] = acc;
        }
        __syncthreads();
        for (int i = tid; i < 160; i += blockDim.x) {
            int b = i / 32, c = i % 32;                 // channel pair (c, c+32)
            int t = c / 16, g = c % 16;
            float v1 = pre_b1[t * 16 + g];
            float v2 = pre_b1[(t + 2) * 16 + g];
            for (int f = 0; f < 16; f++) {
                v1 += eraw[b * 16 + f] * pre_w1[t * 768 + (32 + f) * 16 + g];
                v2 += eraw[b * 16 + f] * pre_w1[(t + 2) * 768 + (32 + f) * 16 + g];
            }
            g_etab2[b * 34 + c] = pk2(v1, v2);
        }
        return;
    }

    __shared__ float w1s[3072];
    for (int i = threadIdx.x; i < 3072; i += blockDim.x) w1s[i] = pre_w1[i];
    __syncthreads();
    int n = blockIdx.x * blockDim.x + threadIdx.x;
    if (n >= NN) return;
    g_deg[n] = 0;

#pragma unroll
    for (int t1 = 0; t1 < 2; t1++) {
        int ta = t1, tb = t1 + 2;
        float xa[16], xb[16];
        const float4* xpa = (const float4*)(atom_x + (size_t)n * 64 + ta * 16);
        const float4* xpb = (const float4*)(atom_x + (size_t)n * 64 + tb * 16);
#pragma unroll
        for (int q = 0; q < 4; q++) {
            float4 v = xpa[q];
            xa[4*q] = v.x; xa[4*q+1] = v.y; xa[4*q+2] = v.z; xa[4*q+3] = v.w;
            float4 w = xpb[q];
            xb[4*q] = w.x; xb[4*q+1] = w.y; xb[4*q+2] = w.z; xb[4*q+3] = w.w;
        }
        float ada[16], asa[16], adb[16], asb[16];
#pragma unroll
        for (int g = 0; g < 16; g++) { ada[g]=0.f; asa[g]=0.f; adb[g]=0.f; asb[g]=0.f; }
#pragma unroll
        for (int f = 0; f < 16; f++) {
            float va = xa[f], vb = xb[f];
#pragma unroll
            for (int g = 0; g < 16; g++) {
                ada[g] += va * w1s[ta * 768 + f * 16 + g];
                asa[g] += va * w1s[ta * 768 + (16 + f) * 16 + g];
                adb[g] += vb * w1s[tb * 768 + f * 16 + g];
                asb[g] += vb * w1s[tb * 768 + (16 + f) * 16 + g];
            }
        }
#pragma unroll
        for (int g = 0; g < 16; g++) {
            g_adst2[(size_t)n * 32 + t1 * 16 + g] = pk2(ada[g], adb[g]);
            g_asrc2[(size_t)n * 32 + t1 * 16 + g] = pk2(asa[g], asb[g]);
        }
    }
}

// ---------------- K2: degree histogram ---------------------------------------------
__global__ void k2_count(const int* __restrict__ dst) {
    int e = blockIdx.x * blockDim.x + threadIdx.x;
    if (e < EE) atomicAdd(&g_deg[dst[e]], 1);
}

// ---------------- K3: exclusive scan (single block, int4) --------------------------
__global__ void k3_scan() {
    __shared__ int wsum[32];
    __shared__ int s_tot;
    int tid = threadIdx.x, lane = tid & 31, wid = tid >> 5;
    int running = 0;
    for (int base = 0; base < NN; base += 4096) {
        int i0 = base + tid * 4;
        int4 v = make_int4(0, 0, 0, 0);
        if (i0 < NN) v = *(const int4*)&g_deg[i0];
        int c0 = v.x, c1 = c0 + v.y, c2 = c1 + v.z, c3 = c2 + v.w;
        int tsum = c3;
        int incl = tsum;
#pragma unroll
        for (int d = 1; d < 32; d <<= 1) {
            int t2 = __shfl_up_sync(0xFFFFFFFFu, incl, d);
            if (lane >= d) incl += t2;
        }
        if (lane == 31) wsum[wid] = incl;
        __syncthreads();
        if (wid == 0) {
            int wv = wsum[lane];
            int wi = wv;
#pragma unroll
            for (int d = 1; d < 32; d <<= 1) {
                int t2 = __shfl_up_sync(0xFFFFFFFFu, wi, d);
                if (lane >= d) wi += t2;
            }
            wsum[lane] = wi - wv;
            if (lane == 31) s_tot = wi;
        }
        __syncthreads();
        int off = running + wsum[wid] + incl - tsum;
        if (i0 < NN) {
            int4 o = make_int4(off, off + c0, off + c1, off + c2);
            *(int4*)&g_rowoff[i0] = o;
            *(int4*)&g_cursor[i0] = o;
        }
        running += s_tot;
        __syncthreads();
    }
    if (tid == 0) g_rowoff[NN] = running;
}

// ---------------- K4: bucket permutation + pack ------------------------------------
__global__ void k4_permute(const int* __restrict__ src, const int* __restrict__ dst,
                           const int* __restrict__ bond) {
    int e = blockIdx.x * blockDim.x + threadIdx.x;
    if (e >= EE) return;
    int slot = atomicAdd(&g_cursor[dst[e]], 1);
    g_epack[slot] = src[e] | (bond[e] << 16);
}

// ---------------- K5: fused edge messages + aggregation ----------------------------
// Lane mapping for the W2 product: tower to=lane>>3, outputs {g0, g0+8}, g0=lane&7.
// h broadcast via per-warp smem rows (stride 20 floats -> LDS.128 bank-disjoint).
__global__ void __launch_bounds__(256) k5_edgeagg(const float* __restrict__ pre_w2,
                                                  const float* __restrict__ pre_b2) {
    __shared__ float w2s[1024];
    __shared__ float b2s[64];
    __shared__ u64 etab2s[5 * 34];
    __shared__ __align__(16) float hbuf[8][2][80];      // [warp][buf][4 towers * 20]
    for (int i = threadIdx.x; i < 1024; i += blockDim.x) w2s[i] = pre_w2[i];
    for (int i = threadIdx.x; i < 64; i += blockDim.x) b2s[i] = pre_b2[i];
    for (int i = threadIdx.x; i < 170; i += blockDim.x) etab2s[i] = g_etab2[i];
    __syncthreads();

    int wid = threadIdx.x >> 5, lane = threadIdx.x & 31;
    int n = blockIdx.x * 8 + wid;
    if (n >= NN) return;

    // h-compute mapping: this lane produces channels (lane, lane+32)
    int th = lane >> 4;                                  // tower of h1 (h2 = th+2)
    int fh = lane & 15;
    u64 adstp = g_adst2[(size_t)n * 32 + lane];

    // output mapping: tower to, outputs g0 and g0+8
    int to = lane >> 3, g0 = lane & 7;
    float wA[16], wB[16];
#pragma unroll
    for (int f = 0; f < 16; f++) {
        wA[f] = w2s[to * 256 + f * 16 + g0];
        wB[f] = w2s[to * 256 + f * 16 + g0 + 8];
    }
    float bA = b2s[to * 16 + g0], bB = b2s[to * 16 + g0 + 8];

    int r0 = g_rowoff[n], r1 = g_rowoff[n + 1];
    float sA = 0.f, sB = 0.f, qA = 0.f, qB = 0.f;
    float mnA = INFINITY, mnB = INFINITY, mxA = -INFINITY, mxB = -INFINITY;

    for (int i = r0; i < r1; i += 32) {
        int pk = 0;
        if (i + lane < r1) pk = g_epack[i + lane];
        int cnt = min(32, r1 - i);
        // depth-2 prefetch of asrc rows
        int p0 = __shfl_sync(0xFFFFFFFFu, pk, 0);
        u64 a0 = __ldg(&g_asrc2[(size_t)(p0 & 0xFFFF) * 32 + lane]);
        int p1 = p0; u64 a1 = a0;
        if (cnt > 1) {
            p1 = __shfl_sync(0xFFFFFFFFu, pk, 1);
            a1 = __ldg(&g_asrc2[(size_t)(p1 & 0xFFFF) * 32 + lane]);
        }
        for (int j = 0; j < cnt; j++) {
            u64 acur = a0; int pcur = p0;
            a0 = a1; p0 = p1;
            if (j + 2 < cnt) {
                p1 = __shfl_sync(0xFFFFFFFFu, pk, j + 2);
                a1 = __ldg(&g_asrc2[(size_t)(p1 & 0xFFFF) * 32 + lane]);
            }
            u64 hsum = add2(adstp, add2(acur, etab2s[(pcur >> 16) * 34 + lane]));
            float h1, h2; up2(h1, h2, hsum);
            h1 = fmaxf(h1, 0.f); h2 = fmaxf(h2, 0.f);
            float* hb = &hbuf[wid][j & 1][0];
            hb[th * 20 + fh]       = h1;                 // channel lane
            hb[(th + 2) * 20 + fh] = h2;                 // channel lane+32
            __syncwarp();
            const float4* hr = (const float4*)&hb[to * 20];
            float4 v0 = hr[0], v1 = hr[1], v2 = hr[2], v3 = hr[3];
            float h[16] = { v0.x, v0.y, v0.z, v0.w, v1.x, v1.y, v1.z, v1.w,
                            v2.x, v2.y, v2.z, v2.w, v3.x, v3.y, v3.z, v3.w };
            float mA = bA, mB = bB;
#pragma unroll
            for (int f = 0; f < 16; f++) {
                mA += h[f] * wA[f];
                mB += h[f] * wB[f];
            }
            sA += mA; qA += mA * mA; mnA = fminf(mnA, mA); mxA = fmaxf(mxA, mA);
            sB += mB; qB += mB * mB; mnB = fminf(mnB, mB); mxB = fmaxf(mxB, mB);
        }
    }

    int deg = r1 - r0;
    float cc = fmaxf((float)deg, 1.f);
    float inv = 1.f / cc;
    float meanA = sA * inv, meanB = sB * inv;
    float stdA = sqrtf(fmaxf(qA * inv - meanA * meanA, 0.f) + 1e-5f);
    float stdB = sqrtf(fmaxf(qB * inv - meanB * meanB, 0.f) + 1e-5f);
    if (deg == 0) { mnA = 0.f; mnB = 0.f; mxA = 0.f; mxB = 0.f; }

    float* ap = g_agg + (size_t)n * 320 + to * 80 + g0;
    ap[0]  = sA; ap[16] = meanA; ap[32] = mnA; ap[48] = mxA; ap[64] = stdA;
    ap[8]  = sB; ap[24] = meanB; ap[40] = mnB; ap[56] = mxB; ap[72] = stdB;
}

// ---------------- K6: post-MLP + lin + LN + residual (R3 version, proven) ----------
#define K6_WARPS 16
#define K6_WSCR 2056
#define K6_SMEM_FLOATS (4 * 4112 + 1024 + 4096 + 320 + K6_WARPS * K6_WSCR)

__global__ void __launch_bounds__(512, 1)
k6_node(const float* __restrict__ atom_x,
        const float* __restrict__ post_w1, const float* __restrict__ post_b1,
        const float* __restrict__ post_w2, const float* __restrict__ post_b2,
        const float* __restrict__ lin_w, const float* __restrict__ lin_b,
        const float* __restrict__ ln_g, const float* __restrict__ ln_b,
        float* __restrict__ out, float avg_log) {
    extern __shared__ float sm[];
    float* w1s  = sm;                    // padded tower stride 4112
    float* w2s  = w1s + 4 * 4112;
    float* lws  = w2s + 1024;
    float* bias = lws + 4096;            // [b1(64) b2(64) lb(64) g(64) b(64)]
    float* scratch = bias + 320;

    int tid = threadIdx.x;
    for (int i = tid; i < 16384; i += 512) {
        int t = i >> 12;
        w1s[t * 4112 + (i & 4095)] = post_w1[i];
    }
    for (int i = tid; i < 1024; i += 512) w2s[i] = post_w2[i];
    for (int i = tid; i < 4096; i += 512) lws[i] = lin_w[i];
    if (tid < 64) {
        bias[tid]       = post_b1[tid];
        bias[64 + tid]  = post_b2[tid];
        bias[128 + tid] = lin_b[tid];
        bias[192 + tid] = ln_g[tid];
        bias[256 + tid] = ln_b[tid];
    }
    __syncthreads();

    int wid = tid >> 5, lane = tid & 31;
    int nb = blockIdx.x * (K6_WARPS * 4) + wid * 4;

    float* ws = scratch + wid * K6_WSCR;

#pragma unroll
    for (int m = 0; m < 4; m++) {
        int n = nb + m;
        if (n < NN) {
            ws[m * 64 + lane]      = atom_x[(size_t)n * 64 + lane];
            ws[m * 64 + lane + 32] = atom_x[(size_t)n * 64 + lane + 32];
            const float* agp = g_agg + (size_t)n * 320;
#pragma unroll
            for (int i = 0; i < 10; i++) ws[256 + m * 320 + lane + 32 * i] = agp[lane + 32 * i];
            if (lane == 0) {
                float cc = fmaxf((float)g_deg[n], 1.f);
                float ldv = logf(cc + 1.f);
                ws[2048 + m * 2]     = ldv / avg_log;
                ws[2048 + m * 2 + 1] = avg_log / ldv;
            }
        }
    }
    __syncwarp();

    int t1 = lane >> 4, f1 = lane & 15;
    int t2 = t1 + 2;
    const float* w1a = w1s + t1 * 4112;
    const float* w1b = w1s + t2 * 4112;

    float aA[4], aB[4], aC[4], bA[4], bB[4], bC[4];
#pragma unroll
    for (int m = 0; m < 4; m++) { aA[m]=0.f; aB[m]=0.f; aC[m]=0.f; bA[m]=0.f; bB[m]=0.f; bC[m]=0.f; }

#pragma unroll 4
    for (int f = 0; f < 16; f++) {
        float wa = w1a[f * 16 + f1];
        float wb = w1b[f * 16 + f1];
#pragma unroll
        for (int m = 0; m < 4; m++) {
            aA[m] += ws[m * 64 + t1 * 16 + f] * wa;
            bA[m] += ws[m * 64 + t2 * 16 + f] * wb;
        }
    }
#pragma unroll 2
    for (int k = 0; k < 80; k++) {
        float wa1 = w1a[(16 + k) * 16 + f1];
        float wb1 = w1a[(96 + k) * 16 + f1];
        float wc1 = w1a[(176 + k) * 16 + f1];
        float wa2 = w1b[(16 + k) * 16 + f1];
        float wb2 = w1b[(96 + k) * 16 + f1];
        float wc2 = w1b[(176 + k) * 16 + f1];
#pragma unroll
        for (int m = 0; m < 4; m++) {
            float v1 = ws[256 + m * 320 + t1 * 80 + k];
            float v2 = ws[256 + m * 320 + t2 * 80 + k];
            aA[m] += v1 * wa1; aB[m] += v1 * wb1; aC[m] += v1 * wc1;
            bA[m] += v2 * wa2; bB[m] += v2 * wb2; bC[m] += v2 * wc2;
        }
    }
#pragma unroll
    for (int m = 0; m < 4; m++) {
        float sc1 = ws[2048 + m * 2], sc2 = ws[2048 + m * 2 + 1];
        float acc1 = bias[lane]      + aA[m] + sc1 * aB[m] + sc2 * aC[m];
        float acc2 = bias[lane + 32] + bA[m] + sc1 * bB[m] + sc2 * bC[m];
        ws[1536 + m * 64 + lane]      = fmaxf(acc1, 0.f);
        ws[1536 + m * 64 + lane + 32] = fmaxf(acc2, 0.f);
    }
    __syncwarp();

    {
        float a1[4], a2[4];
#pragma unroll
        for (int m = 0; m < 4; m++) { a1[m] = bias[64 + lane]; a2[m] = bias[64 + lane + 32]; }
#pragma unroll 4
        for (int f = 0; f < 16; f++) {
            float w_1 = w2s[t1 * 256 + f * 16 + f1];
            float w_2 = w2s[t2 * 256 + f * 16 + f1];
#pragma unroll
            for (int m = 0; m < 4; m++) {
                a1[m] += ws[1536 + m * 64 + t1 * 16 + f] * w_1;
                a2[m] += ws[1536 + m * 64 + t2 * 16 + f] * w_2;
            }
        }
        __syncwarp();
#pragma unroll
        for (int m = 0; m < 4; m++) {
            ws[1792 + m * 64 + lane]      = a1[m];
            ws[1792 + m * 64 + lane + 32] = a2[m];
        }
        __syncwarp();
    }

    float l1[4], l2[4];
#pragma unroll
    for (int m = 0; m < 4; m++) { l1[m] = bias[128 + lane]; l2[m] = bias[128 + lane + 32]; }
#pragma unroll 4
    for (int k = 0; k < 64; k++) {
        float w_1 = lws[k * 64 + lane];
        float w_2 = lws[k * 64 + lane + 32];
#pragma unroll
        for (int m = 0; m < 4; m++) {
            float hv = ws[1792 + m * 64 + k];
            l1[m] += hv * w_1;
            l2[m] += hv * w_2;
        }
    }

#pragma unroll
    for (int m = 0; m < 4; m++) {
        int n = nb + m;
        float v1 = l1[m], v2 = l2[m];
        float ssum = v1 + v2;
#pragma unroll
        for (int d = 16; d; d >>= 1) ssum += __shfl_xor_sync(0xFFFFFFFFu, ssum, d);
        float mu = ssum * (1.f / 64.f);
        float d1 = v1 - mu, d2 = v2 - mu;
        float vs = d1 * d1 + d2 * d2;
#pragma unroll
        for (int d = 16; d; d >>= 1) vs += __shfl_xor_sync(0xFFFFFFFFu, vs, d);
        float rstd = rsqrtf(vs * (1.f / 64.f) + 1e-5f);
        float o1 = d1 * rstd * bias[192 + lane] + bias[256 + lane];
        float o2 = d2 * rstd * bias[192 + lane + 32] + bias[256 + lane + 32];
        if (n < NN) {
            out[(size_t)n * 64 + lane]      = ws[m * 64 + lane]      + fmaxf(o1, 0.f);
            out[(size_t)n * 64 + lane + 32] = ws[m * 64 + lane + 32] + fmaxf(o2, 0.f);
        }
    }
}

// ---------------- launch -----------------------------------------------------------
extern "C" void kernel_launch(void* const* d_in, const int* in_sizes, int n_in,
                              void* d_out, int out_size) {
    const float* atom_x  = (const float*)d_in[0];
    const float* bond_emb= (const float*)d_in[1];
    const float* edge_w  = (const float*)d_in[2];
    const float* edge_b  = (const float*)d_in[3];
    const float* pre_w1  = (const float*)d_in[4];
    const float* pre_b1  = (const float*)d_in[5];
    const float* pre_w2  = (const float*)d_in[6];
    const float* pre_b2  = (const float*)d_in[7];
    const float* post_w1 = (const float*)d_in[8];
    const float* post_b1 = (const float*)d_in[9];
    const float* post_w2 = (const float*)d_in[10];
    const float* post_b2 = (const float*)d_in[11];
    const float* lin_w   = (const float*)d_in[12];
    const float* lin_b   = (const float*)d_in[13];
    const float* ln_g    = (const float*)d_in[14];
    const float* ln_b    = (const float*)d_in[15];
    const int*   bond_x  = (const int*)d_in[16];
    const int*   aei     = (const int*)d_in[17];
    const int*   srcp = aei;
    const int*   dstp = aei + EE;
    float* out = (float*)d_out;

    double md[9] = {0, 5, 15, 30, 25, 15, 7, 2, 1};
    double sacc = 0.0, wacc = 0.0;
    for (int i = 0; i < 9; i++) { sacc += std::log((double)i + 1.0) * md[i]; wacc += md[i]; }
    float avg_log = (float)(sacc / wacc);

    const int k6_smem = K6_SMEM_FLOATS * 4;
    cudaFuncSetAttribute(k6_node, cudaFuncAttributeMaxDynamicSharedMemorySize, k6_smem);

    k1_nodepre<<<NB1 + 1, 128>>>(atom_x, pre_w1, bond_emb, edge_w, edge_b, pre_b1);
    k2_count<<<(EE + 255) / 256, 256>>>(dstp);
    k3_scan<<<1, 1024>>>();
    k4_permute<<<(EE + 255) / 256, 256>>>(srcp, dstp, bond_x);
    k5_edgeagg<<<(NN + 7) / 8, 256>>>(pre_w2, pre_b2);
    k6_node<<<(NN + K6_WARPS * 4 - 1) / (K6_WARPS * 4), 512, k6_smem>>>(
        atom_x, post_w1, post_b1, post_w2, post_b2,
        lin_w, lin_b, ln_g, ln_b, out, avg_log);
}